// round 8
// baseline (speedup 1.0000x reference)
#include <cuda_runtime.h>
#include <cuda_fp16.h>
#include <cstdint>

// BMM_S8T_S8N_F16T persistent hybrid:
// 296 persistent CTAs (2/SM), each loops over tiles; R6 compute structure
// (per 16-row warp slab: IMMA cols 0..71, dp4a cols 72..127) with the NEXT
// tile's loads software-pipelined under the current tile's compute into a
// double-buffered smem tile.
// out[b,m,n] = f32( fp16_round( alpha * sum_k a[b,m,k]*b[b,n,k] ) )

#define MDIM 1024
#define NDIM 1024
#define KDIM 128
#define NTILES 4096         // 8 x 8 x 64
#define NCTAS 296           // 2 per SM on 148 SMs

#define ROWSTRIDE 36        // 32 k-words + 4 pad -> conflict-free banks
#define NI_MMA 9            // IMMA cols 0..71
#define COL_DP 72
#define NI_DP 7             // dp4a cols 72..127

#define PACK4(v) __byte_perm(__byte_perm((v).x, (v).y, 0x0040), \
                             __byte_perm((v).z, (v).w, 0x0040), 0x5410)

__global__ __launch_bounds__(256, 2)
void bmm_s8_persist_kernel(const int* __restrict__ A,
                           const int* __restrict__ Bmat,
                           const float* __restrict__ alpha_p,
                           float* __restrict__ Out) {
    __shared__ uint32_t As[2][128 * ROWSTRIDE];
    __shared__ uint32_t Bs[2][128 * ROWSTRIDE];

    const int tid  = threadIdx.x;
    const int lane = tid & 31;
    const int wid  = tid >> 5;

    const int rb = wid * 16;     // warp slab rows
    const int lq = lane >> 2;    // mma group 0..7
    const int lr = lane & 3;     // mma thread-in-group
    const int g  = lane >> 3;    // dp4a row interleave 0..3
    const int j  = lane & 7;     // dp4a col interleave 0..7

    const float alpha = *alpha_p;

    int t = blockIdx.x;

    // ---- Prologue: load tile t into buffer 0 ----
    {
        const int bn = t & 7, bm = (t >> 3) & 7, bz = t >> 6;
        const int* Ab = A    + ((size_t)bz * MDIM + bm * 128) * KDIM;
        const int* Bb = Bmat + ((size_t)bz * NDIM + bn * 128) * KDIM;
        #pragma unroll
        for (int i = 0; i < 16; i++) {
            int idx = tid + i * 256;
            int row = idx >> 5, col = idx & 31;
            int4 va = *(const int4*)(Ab + row * KDIM + col * 4);
            As[0][row * ROWSTRIDE + col] = PACK4(va);
            int4 vb = *(const int4*)(Bb + row * KDIM + col * 4);
            Bs[0][row * ROWSTRIDE + col] = PACK4(vb);
        }
    }
    __syncthreads();

    int buf = 0;

    while (t < NTILES) {
        const int tn = t + NCTAS;
        const bool pf = (tn < NTILES);
        const int nn = tn & 7, nm = (tn >> 3) & 7, nz = tn >> 6;
        const int* An = A    + ((size_t)nz * MDIM + nm * 128) * KDIM;
        const int* Bn = Bmat + ((size_t)nz * NDIM + nn * 128) * KDIM;

        int4 pa[2], pb[2];   // one prefetch batch in flight (16 regs)

        #define PF_LDG(b) do { if (pf) {                                        \
            _Pragma("unroll")                                                   \
            for (int u = 0; u < 2; u++) {                                       \
                int idx = tid + ((b) * 2 + u) * 256;                            \
                int row = idx >> 5, col = idx & 31;                             \
                pa[u] = *(const int4*)(An + row * KDIM + col * 4);              \
                pb[u] = *(const int4*)(Bn + row * KDIM + col * 4);              \
            } } } while (0)

        #define PF_STS(b) do { if (pf) {                                        \
            _Pragma("unroll")                                                   \
            for (int u = 0; u < 2; u++) {                                       \
                int idx = tid + ((b) * 2 + u) * 256;                            \
                int row = idx >> 5, col = idx & 31;                             \
                As[buf ^ 1][row * ROWSTRIDE + col] = PACK4(pa[u]);              \
                Bs[buf ^ 1][row * ROWSTRIDE + col] = PACK4(pb[u]);              \
            } } } while (0)

        int macc[NI_MMA][4];
        #pragma unroll
        for (int ni = 0; ni < NI_MMA; ni++)
            #pragma unroll
            for (int r = 0; r < 4; r++) macc[ni][r] = 0;

        int dacc[4][NI_DP];
        #pragma unroll
        for (int mi = 0; mi < 4; mi++)
            #pragma unroll
            for (int ni = 0; ni < NI_DP; ni++) dacc[mi][ni] = 0;

        #pragma unroll
        for (int ks = 0; ks < 4; ks++) {
            // ---- chunk A: prefetch batch 2*ks under the IMMA block ----
            PF_LDG(2 * ks);
            {
                uint32_t af[4];
                const uint32_t* p = &As[buf][(rb + lq) * ROWSTRIDE + ks * 8 + lr];
                af[0] = p[0];  af[2] = p[4];
                const uint32_t* p8 = p + 8 * ROWSTRIDE;
                af[1] = p8[0]; af[3] = p8[4];
                #pragma unroll
                for (int ni = 0; ni < NI_MMA; ni++) {
                    const uint32_t* q = &Bs[buf][(ni * 8 + lq) * ROWSTRIDE + ks * 8 + lr];
                    uint32_t b0 = q[0], b1 = q[4];
                    asm volatile(
                        "mma.sync.aligned.m16n8k32.row.col.s32.s8.s8.s32 "
                        "{%0,%1,%2,%3}, {%4,%5,%6,%7}, {%8,%9}, {%0,%1,%2,%3};"
                        : "+r"(macc[ni][0]), "+r"(macc[ni][1]),
                          "+r"(macc[ni][2]), "+r"(macc[ni][3])
                        : "r"(af[0]), "r"(af[1]), "r"(af[2]), "r"(af[3]),
                          "r"(b0), "r"(b1));
                }
            }
            PF_STS(2 * ks);

            // ---- chunk B: prefetch batch 2*ks+1 under the dp4a block ----
            PF_LDG(2 * ks + 1);
            #pragma unroll
            for (int c = 0; c < 2; c++) {
                const int kw = ks * 8 + c * 4;
                uint4 av[4];
                #pragma unroll
                for (int mi = 0; mi < 4; mi++)
                    av[mi] = *(const uint4*)&As[buf][(rb + g + 4 * mi) * ROWSTRIDE + kw];
                #pragma unroll
                for (int ni = 0; ni < NI_DP; ni++) {
                    uint4 bv = *(const uint4*)&Bs[buf][(COL_DP + j + 8 * ni) * ROWSTRIDE + kw];
                    #pragma unroll
                    for (int mi = 0; mi < 4; mi++) {
                        int v = dacc[mi][ni];
                        v = __dp4a((int)av[mi].x, (int)bv.x, v);
                        v = __dp4a((int)av[mi].y, (int)bv.y, v);
                        v = __dp4a((int)av[mi].z, (int)bv.z, v);
                        v = __dp4a((int)av[mi].w, (int)bv.w, v);
                        dacc[mi][ni] = v;
                    }
                }
            }
            PF_STS(2 * ks + 1);
        }

        __syncthreads();   // next buffer fully written; current buffer done

        // ---- Epilogue for tile t (registers -> gmem) ----
        {
            const int bn = t & 7, bm = (t >> 3) & 7, bz = t >> 6;
            float* obase = Out + ((size_t)bz * MDIM + bm * 128) * NDIM + bn * 128;

            #pragma unroll
            for (int ni = 0; ni < NI_MMA; ni++) {
                int c0 = ni * 8 + lr * 2;
                float2 v0;
                v0.x = __half2float(__float2half_rn(alpha * (float)macc[ni][0]));
                v0.y = __half2float(__float2half_rn(alpha * (float)macc[ni][1]));
                *(float2*)(obase + (size_t)(rb + lq) * NDIM + c0) = v0;
                float2 v1;
                v1.x = __half2float(__float2half_rn(alpha * (float)macc[ni][2]));
                v1.y = __half2float(__float2half_rn(alpha * (float)macc[ni][3]));
                *(float2*)(obase + (size_t)(rb + lq + 8) * NDIM + c0) = v1;
            }
            #pragma unroll
            for (int mi = 0; mi < 4; mi++) {
                float* orow = obase + (size_t)(rb + g + 4 * mi) * NDIM;
                #pragma unroll
                for (int ni = 0; ni < NI_DP; ni++) {
                    int col = COL_DP + j + 8 * ni;
                    orow[col] = __half2float(__float2half_rn(alpha * (float)dacc[mi][ni]));
                }
            }
        }

        buf ^= 1;
        t = tn;
        #undef PF_LDG
        #undef PF_STS
    }
}

extern "C" void kernel_launch(void* const* d_in, const int* in_sizes, int n_in,
                              void* d_out, int out_size) {
    // alpha is the size-1 input; the two large tensors are a then b in index order.
    int ai = -1, bi = -1, si = -1;
    for (int i = 0; i < n_in; i++) {
        if (in_sizes[i] == 1) { si = i; }
        else if (ai < 0)      { ai = i; }
        else                  { bi = i; }
    }
    const int*   a     = (const int*)d_in[ai];
    const int*   b     = (const int*)d_in[bi];
    const float* alpha = (const float*)d_in[si];
    float*       out   = (float*)d_out;

    bmm_s8_persist_kernel<<<NCTAS, 256>>>(a, b, alpha, out);
}